// round 3
// baseline (speedup 1.0000x reference)
#include <cuda_runtime.h>
#include <math.h>

// ---------------- problem constants ----------------
#define Bn   4
#define Sn   2048
#define Dn   1024
#define Hn   8
#define LRn  512
#define LRHn 64
#define SHDn 128
#define EXPn 2
#define Kn   4
#define CONVn 1042            // 2*LR + 2*H + EXP
#define NJn   1554            // CONV + LR
#define BSn   8192            // B*S

// ---------------- device scratch (no allocations allowed) ----------------
__device__ float g_proj[(size_t)BSn * NJn];      // x @ w_in^T
__device__ float g_y[(size_t)BSn * CONVn];       // conv+silu output
__device__ float g_xv[(size_t)BSn * Hn * SHDn];  // scan x input
__device__ float g_fv[(size_t)BSn * Hn * SHDn];  // scan f input
__device__ float g_rin[(size_t)BSn * Hn];
__device__ float g_cg[(size_t)BSn * Hn];
__device__ float g_sw[(size_t)3 * Hn * SHDn * SHDn]; // normalized state_w
__device__ float g_out[(size_t)BSn * Hn * SHDn]; // residual + h*Cg
__device__ float g_u[(size_t)BSn * LRn];         // gated+rms'd up proj

// ---------------- tiled SGEMM:  C[m][n] = sum_k A[m][k] * Bm[n][k] ----------------
__device__ __forceinline__ void sgemm_body(const float* __restrict__ A,
                                           const float* __restrict__ Bm,
                                           float* __restrict__ C,
                                           int M, int N, int Kd) {
    __shared__ float As[16][132];
    __shared__ float Bs[16][132];
    const int tid = threadIdx.x;
    const int bm = blockIdx.y * 128;
    const int bn = blockIdx.x * 128;
    const int ar = tid >> 2;          // 0..63
    const int ac = (tid & 3) * 4;     // 0,4,8,12
    const int tx = tid & 15;
    const int ty = tid >> 4;

    float acc[8][8];
#pragma unroll
    for (int i = 0; i < 8; i++)
#pragma unroll
        for (int j = 0; j < 8; j++) acc[i][j] = 0.f;

    for (int k0 = 0; k0 < Kd; k0 += 16) {
#pragma unroll
        for (int i = 0; i < 2; i++) {
            int r = ar + i * 64;
            float4 v = *(const float4*)&A[(size_t)(bm + r) * Kd + k0 + ac];
            As[ac + 0][r] = v.x; As[ac + 1][r] = v.y;
            As[ac + 2][r] = v.z; As[ac + 3][r] = v.w;
        }
#pragma unroll
        for (int i = 0; i < 2; i++) {
            int r = ar + i * 64;
            float4 v = make_float4(0.f, 0.f, 0.f, 0.f);
            if (bn + r < N)
                v = *(const float4*)&Bm[(size_t)(bn + r) * Kd + k0 + ac];
            Bs[ac + 0][r] = v.x; Bs[ac + 1][r] = v.y;
            Bs[ac + 2][r] = v.z; Bs[ac + 3][r] = v.w;
        }
        __syncthreads();
#pragma unroll
        for (int k = 0; k < 16; k++) {
            float4 a0 = *(const float4*)&As[k][ty * 8];
            float4 a1 = *(const float4*)&As[k][ty * 8 + 4];
            float4 b0 = *(const float4*)&Bs[k][tx * 8];
            float4 b1 = *(const float4*)&Bs[k][tx * 8 + 4];
            float ra[8] = {a0.x, a0.y, a0.z, a0.w, a1.x, a1.y, a1.z, a1.w};
            float rb[8] = {b0.x, b0.y, b0.z, b0.w, b1.x, b1.y, b1.z, b1.w};
#pragma unroll
            for (int i = 0; i < 8; i++)
#pragma unroll
                for (int j = 0; j < 8; j++) acc[i][j] += ra[i] * rb[j];
        }
        __syncthreads();
    }
#pragma unroll
    for (int i = 0; i < 8; i++) {
        int m = bm + ty * 8 + i;
#pragma unroll
        for (int j = 0; j < 8; j++) {
            int n = bn + tx * 8 + j;
            if (n < N) C[(size_t)m * N + n] = acc[i][j];
        }
    }
}

__global__ void __launch_bounds__(256) gemm_proj_kernel(const float* __restrict__ x,
                                                        const float* __restrict__ w_in) {
    sgemm_body(x, w_in, g_proj, BSn, NJn, Dn);
}

__global__ void __launch_bounds__(256) gemm_out_kernel(const float* __restrict__ out_w,
                                                       float* __restrict__ C) {
    sgemm_body(g_u, out_w, C, BSn, Dn, LRn);
}

// ---------------- depthwise causal conv (K=4) + SiLU ----------------
__global__ void __launch_bounds__(256) conv_kernel(const float* __restrict__ conv_w) {
    int c = blockIdx.x * 256 + threadIdx.x;
    int b = blockIdx.y;
    if (c >= CONVn) return;
    float w0 = conv_w[c * 4 + 0], w1 = conv_w[c * 4 + 1];
    float w2 = conv_w[c * 4 + 2], w3 = conv_w[c * 4 + 3];
    const float* pin = g_proj + (size_t)b * Sn * NJn + c;
    float* py = g_y + (size_t)b * Sn * CONVn + c;
    float p0 = 0.f, p1 = 0.f, p2 = 0.f;
    for (int s = 0; s < Sn; s++) {
        float p3 = pin[(size_t)s * NJn];
        float v = w0 * p0 + w1 * p1 + w2 * p2 + w3 * p3;
        float sv = v / (1.f + __expf(-v));
        py[(size_t)s * CONVn] = sv;
        p0 = p1; p1 = p2; p2 = p3;
    }
}

// ---------------- per-(b,s) prep: RMS norms, outer products ----------------
__global__ void __launch_bounds__(256) prep_kernel(const float* __restrict__ w_in_norm,
                                                   const float* __restrict__ w_f_norm,
                                                   const float* __restrict__ w_r_norm) {
    const int row = blockIdx.x;          // 0..8191
    const int tid = threadIdx.x;
    const float* y = g_y + (size_t)row * CONVn;
    __shared__ float red[256];
    __shared__ float sc[3];

    float a0 = y[tid], a1 = y[tid + 256];        // inp
    float b0 = y[tid + 512], b1 = y[tid + 768];  // fin

    red[tid] = a0 * a0 + a1 * a1;
    __syncthreads();
    for (int off = 128; off > 0; off >>= 1) {
        if (tid < off) red[tid] += red[tid + off];
        __syncthreads();
    }
    if (tid == 0) sc[0] = rsqrtf(red[0] * (1.f / 512.f) + 1e-6f);
    __syncthreads();

    red[tid] = b0 * b0 + b1 * b1;
    __syncthreads();
    for (int off = 128; off > 0; off >>= 1) {
        if (tid < off) red[tid] += red[tid + off];
        __syncthreads();
    }
    if (tid == 0) {
        sc[1] = rsqrtf(red[0] * (1.f / 512.f) + 1e-6f);
        float ss = 0.f;
        for (int i = 0; i < 8; i++) { float v = y[1024 + i]; ss += v * v; }
        sc[2] = rsqrtf(ss * 0.125f + 1e-6f);
    }
    __syncthreads();

    const float rsi = sc[0], rsf = sc[1], rsr = sc[2];
    const float e0 = y[1040], e1 = y[1041];
    const size_t xb = (size_t)row * (Hn * SHDn);

    {
        float v = a0 * rsi * w_in_norm[tid];
        int hh = tid >> 6, ll = tid & 63;
        g_xv[xb + hh * SHDn + ll] = v * e0;
        g_xv[xb + hh * SHDn + 64 + ll] = v * e1;
        float f = b0 * rsf * w_f_norm[tid];
        g_fv[xb + hh * SHDn + ll] = f * e0;
        g_fv[xb + hh * SHDn + 64 + ll] = f * e1;
    }
    {
        int l = tid + 256;
        float v = a1 * rsi * w_in_norm[l];
        int hh = l >> 6, ll = l & 63;
        g_xv[xb + hh * SHDn + ll] = v * e0;
        g_xv[xb + hh * SHDn + 64 + ll] = v * e1;
        float f = b1 * rsf * w_f_norm[l];
        g_fv[xb + hh * SHDn + ll] = f * e0;
        g_fv[xb + hh * SHDn + 64 + ll] = f * e1;
    }
    if (tid < 8) {
        g_rin[(size_t)row * Hn + tid] = y[1024 + tid] * rsr * w_r_norm[tid];
        g_cg[(size_t)row * Hn + tid]  = y[1032 + tid];
    }
}

// ---------------- normalize state_w (Frobenius per matrix) ----------------
__global__ void __launch_bounds__(256) normsw_kernel(const float* __restrict__ state_w) {
    const int m = blockIdx.x;            // 0..23
    const int tid = threadIdx.x;
    const float* src = state_w + (size_t)m * (SHDn * SHDn);
    float* dst = g_sw + (size_t)m * (SHDn * SHDn);
    __shared__ float red[256];
    __shared__ float sc;
    float ss = 0.f;
    for (int i = tid; i < SHDn * SHDn; i += 256) { float v = src[i]; ss += v * v; }
    red[tid] = ss;
    __syncthreads();
    for (int off = 128; off > 0; off >>= 1) {
        if (tid < off) red[tid] += red[tid + off];
        __syncthreads();
    }
    if (tid == 0) sc = 1.f / fmaxf(sqrtf(red[0]), 1e-12f);
    __syncthreads();
    float scale = sc;
    for (int i = tid; i < SHDn * SHDn; i += 256) dst[i] = src[i] * scale;
}

// ---------------- sequential scan: 32 CTAs (b,h), 384 threads ----------------
// Thread (g,e): g=0 -> W, g=1 -> Fw, g=2 -> Rw; holds column e of its matrix
// in 128 registers. Per step: phase A (g1,g2 matvecs -> f, r*h), barrier,
// phase B (g0 matvec -> h update + output), barrier.
__global__ void __launch_bounds__(384, 1) scan_kernel(const float* __restrict__ res_w) {
    const int bh = blockIdx.x;
    const int b = bh >> 3, h = bh & 7;
    const int t = threadIdx.x;
    const int g = t >> 7;     // 0,1,2
    const int e = t & 127;

    const float* M = g_sw + ((size_t)(g * Hn + h)) * (SHDn * SHDn);
    float wcol[SHDn];
    for (int d = 0; d < SHDn; ++d) wcol[d] = M[d * SHDn + e];

    __shared__ float h_s[2][SHDn];
    __shared__ float rh_s[SHDn];
    __shared__ float f_s[SHDn];

    const size_t base = ((size_t)b * Sn * Hn + h) * SHDn;
    const float* xp = g_xv + base;
    const float* fp = g_fv + base;
    const float* rp = g_rin + (size_t)b * Sn * Hn + h;
    const float* cp = g_cg + (size_t)b * Sn * Hn + h;
    float* op = g_out + base;
    const float rw = res_w[h];

    if (t < SHDn) h_s[0][t] = 0.f;

    float x_t = 0.f, f_t = 0.f, rin_t = 0.f, cg_t = 0.f;
    if (g == 0) { x_t = xp[e]; cg_t = cp[0]; }
    else if (g == 1) { f_t = fp[e]; }
    else { rin_t = rp[0]; }
    __syncthreads();

    int cur = 0;
    for (int s = 0; s < Sn; ++s) {
        const int sn = (s + 1 < Sn) ? (s + 1) : s;   // clamped prefetch index
        const float* hc = h_s[cur];
        if (g == 2) {
            float acc = rin_t;
            const float4* h4 = (const float4*)hc;
#pragma unroll 16
            for (int d4 = 0; d4 < 32; ++d4) {
                float4 hv = h4[d4];
                acc += hv.x * wcol[4 * d4 + 0] + hv.y * wcol[4 * d4 + 1]
                     + hv.z * wcol[4 * d4 + 2] + hv.w * wcol[4 * d4 + 3];
            }
            float r = 1.f / (1.f + __expf(-acc));
            rh_s[e] = r * hc[e];
            rin_t = rp[(size_t)sn * Hn];
        } else if (g == 1) {
            float acc = f_t;
            const float4* h4 = (const float4*)hc;
#pragma unroll 16
            for (int d4 = 0; d4 < 32; ++d4) {
                float4 hv = h4[d4];
                acc += hv.x * wcol[4 * d4 + 0] + hv.y * wcol[4 * d4 + 1]
                     + hv.z * wcol[4 * d4 + 2] + hv.w * wcol[4 * d4 + 3];
            }
            f_s[e] = 1.f / (1.f + __expf(-acc));
            f_t = fp[(size_t)sn * Hn * SHDn + e];
        }
        __syncthreads();
        if (g == 0) {
            float acc = x_t;
            const float4* r4 = (const float4*)rh_s;
#pragma unroll 16
            for (int d4 = 0; d4 < 32; ++d4) {
                float4 hv = r4[d4];
                acc += hv.x * wcol[4 * d4 + 0] + hv.y * wcol[4 * d4 + 1]
                     + hv.z * wcol[4 * d4 + 2] + hv.w * wcol[4 * d4 + 3];
            }
            float ht = tanhf(acc);
            float f = f_s[e];
            float hn = f * hc[e] + (1.f - f) * ht;
            h_s[cur ^ 1][e] = hn;
            op[(size_t)s * Hn * SHDn + e] = rw * x_t + hn * cg_t;
            x_t = xp[(size_t)sn * Hn * SHDn + e];
            cg_t = cp[(size_t)sn * Hn];
        }
        __syncthreads();
        cur ^= 1;
    }
}

// ---------------- up projection + gate + RMS ----------------
__global__ void __launch_bounds__(256) up_kernel(const float* __restrict__ up_w,
                                                 const float* __restrict__ w_g_norm) {
    const int row = blockIdx.x;
    const int tid = threadIdx.x;
    __shared__ float o_s[Hn * SHDn];     // 1024
    __shared__ float uw[64][132];        // up_w padded
    __shared__ float red[256];

    const float* orow = g_out + (size_t)row * (Hn * SHDn);
#pragma unroll
    for (int i = 0; i < 4; i++) o_s[tid + i * 256] = orow[tid + i * 256];
#pragma unroll
    for (int i = 0; i < 32; i++) {
        int id = tid + i * 256;              // 0..8191
        int j = id >> 7, d = id & 127;
        uw[j][d] = up_w[id];
    }
    __syncthreads();

    const int jj = tid & 63;
    const int h0 = tid >> 6;  // 0..3 ; second output head = h0+4
    float u0 = 0.f, u1 = 0.f;
    const float4* o4 = (const float4*)o_s;
#pragma unroll 16
    for (int d4 = 0; d4 < 32; ++d4) {
        float4 wv = *(const float4*)&uw[jj][d4 * 4];
        float4 ov0 = o4[h0 * 32 + d4];
        float4 ov1 = o4[(h0 + 4) * 32 + d4];
        u0 += ov0.x * wv.x + ov0.y * wv.y + ov0.z * wv.z + ov0.w * wv.w;
        u1 += ov1.x * wv.x + ov1.y * wv.y + ov1.z * wv.z + ov1.w * wv.w;
    }
    float g0v = g_proj[(size_t)row * NJn + CONVn + tid];
    float g1v = g_proj[(size_t)row * NJn + CONVn + tid + 256];
    u0 *= g0v / (1.f + __expf(-g0v));
    u1 *= g1v / (1.f + __expf(-g1v));

    red[tid] = u0 * u0 + u1 * u1;
    __syncthreads();
    for (int off = 128; off > 0; off >>= 1) {
        if (tid < off) red[tid] += red[tid + off];
        __syncthreads();
    }
    float rs = rsqrtf(red[0] * (1.f / 512.f) + 1e-6f);
    g_u[(size_t)row * LRn + tid]       = u0 * rs * w_g_norm[tid];
    g_u[(size_t)row * LRn + tid + 256] = u1 * rs * w_g_norm[tid + 256];
}

// ---------------- launch ----------------
extern "C" void kernel_launch(void* const* d_in, const int* in_sizes, int n_in,
                              void* d_out, int out_size) {
    const float* x        = (const float*)d_in[0];
    const float* w_in     = (const float*)d_in[1];
    const float* conv_w   = (const float*)d_in[2];
    const float* state_w  = (const float*)d_in[3];
    const float* up_w     = (const float*)d_in[4];
    const float* out_w    = (const float*)d_in[5];
    const float* res_w    = (const float*)d_in[6];
    const float* w_in_nrm = (const float*)d_in[7];
    const float* w_f_nrm  = (const float*)d_in[8];
    const float* w_r_nrm  = (const float*)d_in[9];
    const float* w_g_nrm  = (const float*)d_in[10];
    float* out = (float*)d_out;

    normsw_kernel<<<24, 256>>>(state_w);
    gemm_proj_kernel<<<dim3((NJn + 127) / 128, BSn / 128), 256>>>(x, w_in);
    conv_kernel<<<dim3((CONVn + 255) / 256, Bn), 256>>>(conv_w);
    prep_kernel<<<BSn, 256>>>(w_in_nrm, w_f_nrm, w_r_nrm);
    scan_kernel<<<Bn * Hn, 384>>>(res_w);
    up_kernel<<<BSn, 256>>>(up_w, w_g_nrm);
    gemm_out_kernel<<<dim3(Dn / 128, BSn / 128), 256>>>(out_w, out);
}

// round 4
// speedup vs baseline: 1.5251x; 1.5251x over previous
#include <cuda_runtime.h>
#include <math.h>

// ---------------- problem constants ----------------
#define Bn   4
#define Sn   2048
#define Dn   1024
#define Hn   8
#define LRn  512
#define LRHn 64
#define SHDn 128
#define EXPn 2
#define Kn   4
#define CONVn 1042            // 2*LR + 2*H + EXP
#define NJn   1554            // CONV + LR
#define BSn   8192            // B*S

typedef unsigned long long ull;

// ---------------- packed f32x2 helpers (Blackwell FFMA2) ----------------
__device__ __forceinline__ ull d_ffma2(ull a, ull b, ull c) {
    ull d;
    asm("fma.rn.f32x2 %0, %1, %2, %3;" : "=l"(d) : "l"(a), "l"(b), "l"(c));
    return d;
}
__device__ __forceinline__ ull f2u(float x, float y) {
    ull u; asm("mov.b64 %0, {%1, %2};" : "=l"(u) : "f"(x), "f"(y)); return u;
}
__device__ __forceinline__ float2 u2f(ull u) {
    float2 f; asm("mov.b64 {%0, %1}, %2;" : "=f"(f.x), "=f"(f.y) : "l"(u)); return f;
}
__device__ __forceinline__ float d_tanh(float x) {
    float r; asm("tanh.approx.f32 %0, %1;" : "=f"(r) : "f"(x)); return r;
}
__device__ __forceinline__ float d_sigmoid(float x) {
    return __fdividef(1.f, 1.f + __expf(-x));
}

// ---------------- device scratch (no allocations allowed) ----------------
__device__ float g_proj[(size_t)BSn * NJn];      // x @ w_in^T
__device__ float g_y[(size_t)BSn * CONVn];       // conv+silu output
__device__ float g_xv[(size_t)BSn * Hn * SHDn];  // scan x input
__device__ float g_fv[(size_t)BSn * Hn * SHDn];  // scan f input
__device__ float g_rin[(size_t)BSn * Hn];
__device__ float g_cg[(size_t)BSn * Hn];
__device__ float g_sw[(size_t)3 * Hn * SHDn * SHDn]; // normalized state_w
__device__ float g_out[(size_t)BSn * Hn * SHDn]; // residual + h*Cg
__device__ float g_u[(size_t)BSn * LRn];         // gated+rms'd up proj

// ---------------- tiled SGEMM with FFMA2:  C[m][n] = sum_k A[m][k]*Bm[n][k] --------
// BM=BN=128, BK=16, 256 threads, 8x8 microtile (as 8x4 packed float2),
// register-prefetch double buffering.
__device__ __forceinline__ void sgemm_body(const float* __restrict__ A,
                                           const float* __restrict__ Bm,
                                           float* __restrict__ C,
                                           int M, int N, int Kd) {
    __shared__ float As[16][132];
    __shared__ float Bs[16][132];
    const int tid = threadIdx.x;
    const int bm = blockIdx.y * 128;
    const int bn = blockIdx.x * 128;
    const int ar = tid >> 2;          // 0..63
    const int ac = (tid & 3) * 4;     // 0,4,8,12
    const int tx = tid & 15;
    const int ty = tid >> 4;

    ull acc[8][4];
#pragma unroll
    for (int i = 0; i < 8; i++)
#pragma unroll
        for (int j = 0; j < 4; j++) acc[i][j] = 0ull;

    float4 pa[2], pb[2];
    // prologue load k0 = 0
#pragma unroll
    for (int i = 0; i < 2; i++) {
        int r = ar + i * 64;
        pa[i] = *(const float4*)&A[(size_t)(bm + r) * Kd + ac];
        pb[i] = make_float4(0.f, 0.f, 0.f, 0.f);
        if (bn + r < N) pb[i] = *(const float4*)&Bm[(size_t)(bn + r) * Kd + ac];
    }

    for (int k0 = 0; k0 < Kd; k0 += 16) {
#pragma unroll
        for (int i = 0; i < 2; i++) {
            int r = ar + i * 64;
            As[ac + 0][r] = pa[i].x; As[ac + 1][r] = pa[i].y;
            As[ac + 2][r] = pa[i].z; As[ac + 3][r] = pa[i].w;
            Bs[ac + 0][r] = pb[i].x; Bs[ac + 1][r] = pb[i].y;
            Bs[ac + 2][r] = pb[i].z; Bs[ac + 3][r] = pb[i].w;
        }
        __syncthreads();
        if (k0 + 16 < Kd) {
#pragma unroll
            for (int i = 0; i < 2; i++) {
                int r = ar + i * 64;
                pa[i] = *(const float4*)&A[(size_t)(bm + r) * Kd + k0 + 16 + ac];
                pb[i] = make_float4(0.f, 0.f, 0.f, 0.f);
                if (bn + r < N)
                    pb[i] = *(const float4*)&Bm[(size_t)(bn + r) * Kd + k0 + 16 + ac];
            }
        }
#pragma unroll
        for (int k = 0; k < 16; k++) {
            float4 a0 = *(const float4*)&As[k][ty * 8];
            float4 a1 = *(const float4*)&As[k][ty * 8 + 4];
            const ull* bp = (const ull*)&Bs[k][tx * 8];
            ull b0 = bp[0], b1 = bp[1], b2 = bp[2], b3 = bp[3];
            float av[8] = {a0.x, a0.y, a0.z, a0.w, a1.x, a1.y, a1.z, a1.w};
#pragma unroll
            for (int i = 0; i < 8; i++) {
                ull ad = f2u(av[i], av[i]);
                acc[i][0] = d_ffma2(ad, b0, acc[i][0]);
                acc[i][1] = d_ffma2(ad, b1, acc[i][1]);
                acc[i][2] = d_ffma2(ad, b2, acc[i][2]);
                acc[i][3] = d_ffma2(ad, b3, acc[i][3]);
            }
        }
        __syncthreads();
    }
#pragma unroll
    for (int i = 0; i < 8; i++) {
        int m = bm + ty * 8 + i;
#pragma unroll
        for (int j = 0; j < 4; j++) {
            float2 v = u2f(acc[i][j]);
            int n = bn + tx * 8 + 2 * j;
            if (n < N)     C[(size_t)m * N + n]     = v.x;
            if (n + 1 < N) C[(size_t)m * N + n + 1] = v.y;
        }
    }
}

__global__ void __launch_bounds__(256) gemm_proj_kernel(const float* __restrict__ x,
                                                        const float* __restrict__ w_in) {
    sgemm_body(x, w_in, g_proj, BSn, NJn, Dn);
}

__global__ void __launch_bounds__(256) gemm_out_kernel(const float* __restrict__ out_w,
                                                       float* __restrict__ C) {
    sgemm_body(g_u, out_w, C, BSn, Dn, LRn);
}

// ---------------- depthwise causal conv (K=4) + SiLU ----------------
__global__ void __launch_bounds__(256) conv_kernel(const float* __restrict__ conv_w) {
    int c = blockIdx.x * 256 + threadIdx.x;
    int b = blockIdx.y;
    if (c >= CONVn) return;
    float w0 = conv_w[c * 4 + 0], w1 = conv_w[c * 4 + 1];
    float w2 = conv_w[c * 4 + 2], w3 = conv_w[c * 4 + 3];
    const float* pin = g_proj + (size_t)b * Sn * NJn + c;
    float* py = g_y + (size_t)b * Sn * CONVn + c;
    float p0 = 0.f, p1 = 0.f, p2 = 0.f;
    for (int s = 0; s < Sn; s++) {
        float p3 = pin[(size_t)s * NJn];
        float v = w0 * p0 + w1 * p1 + w2 * p2 + w3 * p3;
        float sv = v / (1.f + __expf(-v));
        py[(size_t)s * CONVn] = sv;
        p0 = p1; p1 = p2; p2 = p3;
    }
}

// ---------------- per-(b,s) prep: RMS norms, outer products ----------------
__global__ void __launch_bounds__(256) prep_kernel(const float* __restrict__ w_in_norm,
                                                   const float* __restrict__ w_f_norm,
                                                   const float* __restrict__ w_r_norm) {
    const int row = blockIdx.x;          // 0..8191
    const int tid = threadIdx.x;
    const float* y = g_y + (size_t)row * CONVn;
    __shared__ float red[256];
    __shared__ float sc[3];

    float a0 = y[tid], a1 = y[tid + 256];        // inp
    float b0 = y[tid + 512], b1 = y[tid + 768];  // fin

    red[tid] = a0 * a0 + a1 * a1;
    __syncthreads();
    for (int off = 128; off > 0; off >>= 1) {
        if (tid < off) red[tid] += red[tid + off];
        __syncthreads();
    }
    if (tid == 0) sc[0] = rsqrtf(red[0] * (1.f / 512.f) + 1e-6f);
    __syncthreads();

    red[tid] = b0 * b0 + b1 * b1;
    __syncthreads();
    for (int off = 128; off > 0; off >>= 1) {
        if (tid < off) red[tid] += red[tid + off];
        __syncthreads();
    }
    if (tid == 0) {
        sc[1] = rsqrtf(red[0] * (1.f / 512.f) + 1e-6f);
        float ss = 0.f;
        for (int i = 0; i < 8; i++) { float v = y[1024 + i]; ss += v * v; }
        sc[2] = rsqrtf(ss * 0.125f + 1e-6f);
    }
    __syncthreads();

    const float rsi = sc[0], rsf = sc[1], rsr = sc[2];
    const float e0 = y[1040], e1 = y[1041];
    const size_t xb = (size_t)row * (Hn * SHDn);

    {
        float v = a0 * rsi * w_in_norm[tid];
        int hh = tid >> 6, ll = tid & 63;
        g_xv[xb + hh * SHDn + ll] = v * e0;
        g_xv[xb + hh * SHDn + 64 + ll] = v * e1;
        float f = b0 * rsf * w_f_norm[tid];
        g_fv[xb + hh * SHDn + ll] = f * e0;
        g_fv[xb + hh * SHDn + 64 + ll] = f * e1;
    }
    {
        int l = tid + 256;
        float v = a1 * rsi * w_in_norm[l];
        int hh = l >> 6, ll = l & 63;
        g_xv[xb + hh * SHDn + ll] = v * e0;
        g_xv[xb + hh * SHDn + 64 + ll] = v * e1;
        float f = b1 * rsf * w_f_norm[l];
        g_fv[xb + hh * SHDn + ll] = f * e0;
        g_fv[xb + hh * SHDn + 64 + ll] = f * e1;
    }
    if (tid < 8) {
        g_rin[(size_t)row * Hn + tid] = y[1024 + tid] * rsr * w_r_norm[tid];
        g_cg[(size_t)row * Hn + tid]  = y[1032 + tid];
    }
}

// ---------------- normalize state_w (Frobenius per matrix) ----------------
__global__ void __launch_bounds__(256) normsw_kernel(const float* __restrict__ state_w) {
    const int m = blockIdx.x;            // 0..23
    const int tid = threadIdx.x;
    const float* src = state_w + (size_t)m * (SHDn * SHDn);
    float* dst = g_sw + (size_t)m * (SHDn * SHDn);
    __shared__ float red[256];
    __shared__ float sc;
    float ss = 0.f;
    for (int i = tid; i < SHDn * SHDn; i += 256) { float v = src[i]; ss += v * v; }
    red[tid] = ss;
    __syncthreads();
    for (int off = 128; off > 0; off >>= 1) {
        if (tid < off) red[tid] += red[tid + off];
        __syncthreads();
    }
    if (tid == 0) sc = 1.f / fmaxf(sqrtf(red[0]), 1e-12f);
    __syncthreads();
    float scale = sc;
    for (int i = tid; i < SHDn * SHDn; i += 256) dst[i] = src[i] * scale;
}

// ---------------- packed matvec: 128-dot with 4 packed accumulators ----------------
// wu[64]: packed column pairs; hv: 128 floats in shared (uniform address -> broadcast)
__device__ __forceinline__ float matvec128(const float* hv, const ull* wu, float bias) {
    ull a0 = 0ull, a1 = 0ull, a2 = 0ull, a3 = 0ull;
    const ull* h2 = (const ull*)hv;
#pragma unroll
    for (int i = 0; i < 16; i++) {
        a0 = d_ffma2(h2[4 * i + 0], wu[4 * i + 0], a0);
        a1 = d_ffma2(h2[4 * i + 1], wu[4 * i + 1], a1);
        a2 = d_ffma2(h2[4 * i + 2], wu[4 * i + 2], a2);
        a3 = d_ffma2(h2[4 * i + 3], wu[4 * i + 3], a3);
    }
    float2 f0 = u2f(a0), f1 = u2f(a1), f2 = u2f(a2), f3 = u2f(a3);
    return bias + ((f0.x + f0.y) + (f1.x + f1.y)) + ((f2.x + f2.y) + (f3.x + f3.y));
}

// ---------------- sequential scan: 32 CTAs (b,h), 384 threads ----------------
__global__ void __launch_bounds__(384, 1) scan_kernel(const float* __restrict__ res_w) {
    const int bh = blockIdx.x;
    const int b = bh >> 3, h = bh & 7;
    const int t = threadIdx.x;
    const int g = t >> 7;     // 0 -> W, 1 -> Fw, 2 -> Rw
    const int e = t & 127;

    const float* M = g_sw + ((size_t)(g * Hn + h)) * (SHDn * SHDn);
    ull wu[64];
    for (int d = 0; d < 64; ++d)
        wu[d] = f2u(M[(2 * d) * SHDn + e], M[(2 * d + 1) * SHDn + e]);

    __shared__ float h_s[2][SHDn];
    __shared__ float rh_s[SHDn];
    __shared__ float f_s[SHDn];

    const size_t base = ((size_t)b * Sn * Hn + h) * SHDn;
    const float* xp = g_xv + base;
    const float* fp = g_fv + base;
    const float* rp = g_rin + (size_t)b * Sn * Hn + h;
    const float* cp = g_cg + (size_t)b * Sn * Hn + h;
    float* op = g_out + base;
    const float rw = res_w[h];

    if (t < SHDn) h_s[0][t] = 0.f;

    float x_t = 0.f, f_t = 0.f, rin_t = 0.f, cg_t = 0.f;
    if (g == 0) { x_t = xp[e]; cg_t = cp[0]; }
    else if (g == 1) { f_t = fp[e]; }
    else { rin_t = rp[0]; }
    __syncthreads();

    int cur = 0;
    for (int s = 0; s < Sn; ++s) {
        const int sn = (s + 1 < Sn) ? (s + 1) : s;   // clamped prefetch index
        const float* hc = h_s[cur];
        if (g == 2) {
            float acc = matvec128(hc, wu, rin_t);
            rh_s[e] = d_sigmoid(acc) * hc[e];
            rin_t = rp[(size_t)sn * Hn];
        } else if (g == 1) {
            float acc = matvec128(hc, wu, f_t);
            f_s[e] = d_sigmoid(acc);
            f_t = fp[(size_t)sn * Hn * SHDn + e];
        }
        __syncthreads();
        if (g == 0) {
            float acc = matvec128(rh_s, wu, x_t);
            float ht = d_tanh(acc);
            float f = f_s[e];
            float hn = f * hc[e] + (1.f - f) * ht;
            h_s[cur ^ 1][e] = hn;
            op[(size_t)s * Hn * SHDn + e] = rw * x_t + hn * cg_t;
            x_t = xp[(size_t)sn * Hn * SHDn + e];
            cg_t = cp[(size_t)sn * Hn];
        }
        __syncthreads();
        cur ^= 1;
    }
}

// ---------------- up projection + gate + RMS ----------------
__global__ void __launch_bounds__(256) up_kernel(const float* __restrict__ up_w,
                                                 const float* __restrict__ w_g_norm) {
    const int row = blockIdx.x;
    const int tid = threadIdx.x;
    __shared__ float o_s[Hn * SHDn];     // 1024
    __shared__ float uw[64][132];        // up_w padded
    __shared__ float red[256];

    const float* orow = g_out + (size_t)row * (Hn * SHDn);
#pragma unroll
    for (int i = 0; i < 4; i++) o_s[tid + i * 256] = orow[tid + i * 256];
#pragma unroll
    for (int i = 0; i < 32; i++) {
        int id = tid + i * 256;              // 0..8191
        int j = id >> 7, d = id & 127;
        uw[j][d] = up_w[id];
    }
    __syncthreads();

    const int jj = tid & 63;
    const int h0 = tid >> 6;  // 0..3 ; second output head = h0+4
    float u0 = 0.f, u1 = 0.f;
    const float4* o4 = (const float4*)o_s;
#pragma unroll 16
    for (int d4 = 0; d4 < 32; ++d4) {
        float4 wv = *(const float4*)&uw[jj][d4 * 4];
        float4 ov0 = o4[h0 * 32 + d4];
        float4 ov1 = o4[(h0 + 4) * 32 + d4];
        u0 += ov0.x * wv.x + ov0.y * wv.y + ov0.z * wv.z + ov0.w * wv.w;
        u1 += ov1.x * wv.x + ov1.y * wv.y + ov1.z * wv.z + ov1.w * wv.w;
    }
    float g0v = g_proj[(size_t)row * NJn + CONVn + tid];
    float g1v = g_proj[(size_t)row * NJn + CONVn + tid + 256];
    u0 *= g0v / (1.f + __expf(-g0v));
    u1 *= g1v / (1.f + __expf(-g1v));

    red[tid] = u0 * u0 + u1 * u1;
    __syncthreads();
    for (int off = 128; off > 0; off >>= 1) {
        if (tid < off) red[tid] += red[tid + off];
        __syncthreads();
    }
    float rs = rsqrtf(red[0] * (1.f / 512.f) + 1e-6f);
    g_u[(size_t)row * LRn + tid]       = u0 * rs * w_g_norm[tid];
    g_u[(size_t)row * LRn + tid + 256] = u1 * rs * w_g_norm[tid + 256];
}

// ---------------- launch ----------------
extern "C" void kernel_launch(void* const* d_in, const int* in_sizes, int n_in,
                              void* d_out, int out_size) {
    const float* x        = (const float*)d_in[0];
    const float* w_in     = (const float*)d_in[1];
    const float* conv_w   = (const float*)d_in[2];
    const float* state_w  = (const float*)d_in[3];
    const float* up_w     = (const float*)d_in[4];
    const float* out_w    = (const float*)d_in[5];
    const float* res_w    = (const float*)d_in[6];
    const float* w_in_nrm = (const float*)d_in[7];
    const float* w_f_nrm  = (const float*)d_in[8];
    const float* w_r_nrm  = (const float*)d_in[9];
    const float* w_g_nrm  = (const float*)d_in[10];
    float* out = (float*)d_out;

    normsw_kernel<<<24, 256>>>(state_w);
    gemm_proj_kernel<<<dim3((NJn + 127) / 128, BSn / 128), 256>>>(x, w_in);
    conv_kernel<<<dim3((CONVn + 255) / 256, Bn), 256>>>(conv_w);
    prep_kernel<<<BSn, 256>>>(w_in_nrm, w_f_nrm, w_r_nrm);
    scan_kernel<<<Bn * Hn, 384>>>(res_w);
    up_kernel<<<BSn, 256>>>(up_w, w_g_nrm);
    gemm_out_kernel<<<dim3(Dn / 128, BSn / 128), 256>>>(out_w, out);
}